// round 10
// baseline (speedup 1.0000x reference)
#include <cuda_runtime.h>
#include <cuda_bf16.h>
#include <cstdint>

// Per-class greedy NMS, round 10: fused persistent kernel, TMA filter with
// contiguous chunk ownership and full-depth (4-buffer) upfront prefetch.
// Phase 1: each block owns a contiguous run of ceil(nchunks/grid) 8KB chunks,
//   issues ALL of them immediately (ring of 4 smem buffers), scans from smem,
//   emits (score,idx) pairs with score > FINE_LO into per-class buffers.
//   Blocks 0..C-1 (which run phase 2 after the barrier) are permuted to the
//   end of the assignment so they never carry the remainder chunk.
// Global software barrier (888 blocks, 6/SM co-resident).
// Phase 2 (blocks 0..C-1): rank-scatter -> Mp-bounded triangular IoU
//   adjacency (SMSP-balanced) -> 2-sync Jacobi fixpoint -> popcount writeout.
// Exact raw-sweep fallback preserved.

#define MAX_C    80
#define CAPBUF   256
#define NB_FB    2048
#define TOPM     192
#define MCAP     256
#define K_OUT    100
#define NT       256
#define NBLOCKS  888
#define SCORE_T  0.05f
#define IOU_T    0.5f
#define FINE_LO  0.996f

#define NBUF         4
#define CHUNK_FLOATS 2048
#define CHUNK_BYTES  8192
#define CHUNK_F4     512

__device__ unsigned long long g_pairs[MAX_C * CAPBUF];
__device__ unsigned int       g_cnt[MAX_C];   // zero at load; restored each call
__device__ unsigned int       g_bar;
__device__ unsigned int       g_done;

__device__ __forceinline__ unsigned long long make_key(float s, unsigned i) {
    return ((unsigned long long)__float_as_uint(s) << 32)
         | (unsigned long long)(0xFFFFFFFFu - i);
}

__device__ __forceinline__ uint32_t smem_u32(const void* p) {
    uint32_t a;
    asm("{ .reg .u64 t; cvta.to.shared.u64 t, %1; cvt.u32.u64 %0, t; }"
        : "=r"(a) : "l"(p));
    return a;
}

__device__ __forceinline__ void mbar_init(uint32_t mbar, unsigned count) {
    asm volatile("mbarrier.init.shared.b64 [%0], %1;"
                 :: "r"(mbar), "r"(count) : "memory");
}

__device__ __forceinline__ void mbar_wait(uint32_t mbar, unsigned parity) {
    asm volatile(
        "{\n\t.reg .pred P;\n\t"
        "W_%=:\n\t"
        "mbarrier.try_wait.parity.acquire.cta.shared::cta.b64 P, [%0], %1, 0x989680;\n\t"
        "@!P bra W_%=;\n\t}"
        :: "r"(mbar), "r"(parity) : "memory");
}

__device__ __forceinline__ void tma_issue(uint32_t smem_dst,
                                          const float* __restrict__ gsrc,
                                          uint32_t mbar) {
    asm volatile("mbarrier.arrive.expect_tx.shared.b64 _, [%0], %1;"
                 :: "r"(mbar), "r"((unsigned)CHUNK_BYTES) : "memory");
    asm volatile(
        "cp.async.bulk.shared::cluster.global.mbarrier::complete_tx::bytes "
        "[%0], [%1], %2, [%3];"
        :: "r"(smem_dst), "l"(gsrc), "r"((unsigned)CHUNK_BYTES), "r"(mbar)
        : "memory");
}

__device__ __forceinline__ void emitv(float4 v, int flat0, int C,
                                      unsigned magicC) {
    float m = fmaxf(fmaxf(v.x, v.y), fmaxf(v.z, v.w));
    if (m > FINE_LO) {
        float ss[4] = {v.x, v.y, v.z, v.w};
        #pragma unroll
        for (int u = 0; u < 4; ++u) {
            if (ss[u] > FINE_LO) {
                int flat = flat0 + u;
                unsigned q = (unsigned)(((unsigned long long)(unsigned)flat
                                         * magicC) >> 32);
                int r = flat - (int)q * C;
                if (r < 0)     { --q; r += C; }
                while (r >= C) { ++q; r -= C; }
                unsigned pos = atomicAdd(&g_cnt[r], 1u);
                if (pos < CAPBUF)
                    g_pairs[r * CAPBUF + pos] = make_key(ss[u], q);
            }
        }
    }
}

__device__ __forceinline__ void warp_cutoff(const unsigned int* hist,
                                            int nbucket, int bmin, int* s_b0) {
    const int lane = threadIdx.x;
    int cum = 0, b0 = bmin;
    for (int hi = nbucket - 1; hi >= bmin; hi -= 32) {
        int b = hi - lane;
        int v = (b >= bmin) ? (int)hist[b] : 0;
        int p = v;
        #pragma unroll
        for (int off = 1; off < 32; off <<= 1) {
            int t = __shfl_up_sync(0xFFFFFFFFu, p, off);
            if (lane >= off) p += t;
        }
        unsigned m = __ballot_sync(0xFFFFFFFFu, cum + p >= TOPM);
        if (m) { b0 = hi - (__ffs(m) - 1); break; }
        cum += __shfl_sync(0xFFFFFFFFu, p, 31);
    }
    if (lane == 0) *s_b0 = b0;
}

struct SmemNMS {
    unsigned long long keys[MCAP];
    float4       box[MCAP];
    float        area[MCAP];
    float        score[MCAP];
    unsigned int hist[NB_FB];       // fallback only
    unsigned int keepw[8];
    unsigned int cnt2;
    int          b0, kept, chgr;
};

struct __align__(128) SmemAll {
    union {
        float4  buf[NBUF][CHUNK_F4];   // phase 1: 4 x 8KB TMA ring
        SmemNMS nms;                   // phase 2
    };
    unsigned long long mbar[NBUF];
};

// rank-scatter + Mp-bounded balanced triangular adjacency + greedy fixpoint.
__device__ __forceinline__ void nms_core(SmemNMS* sm,
                                         const float4* __restrict__ boxes,
                                         int Mp, int tid) {
    const unsigned long long mykey = sm->keys[tid];
    const ulonglong2* __restrict__ k2 = (const ulonglong2*)sm->keys;
    const int jmax = (Mp + 1) >> 1;
    int rank = 0;
    #pragma unroll 4
    for (int j = 0; j < jmax; ++j) {
        ulonglong2 kk = k2[j];
        rank += (kk.x > mykey) ? 1 : 0;
        rank += (kk.y > mykey) ? 1 : 0;
    }
    if (tid < Mp) {
        int idx = (int)(0xFFFFFFFFu - (unsigned)(mykey & 0xFFFFFFFFull));
        float4 b = __ldg(boxes + idx);
        sm->box[rank]   = b;
        sm->area[rank]  = (b.z - b.x) * (b.w - b.y);
        sm->score[rank] = __uint_as_float((unsigned)(mykey >> 32));
    }
    __syncthreads();

    const int w    = tid >> 5;
    const int lane = tid & 31;
    const int wb   = (w < 4) ? w : 11 - w;   // SMSP-balanced row blocks
    const int row  = wb * 32 + lane;
    const int nwB  = (Mp + 31) >> 5;
    const int wlim = min(wb + 1, nwB);

    const float4 mb  = sm->box[row];
    const float  mya = sm->area[row] + 1e-8f;
    unsigned adjw[8] = {0u,0u,0u,0u,0u,0u,0u,0u};

    // IoU > 0.5  <=>  3*inter > a_i + a_j + 1e-8 (division-free, exact)
    #pragma unroll
    for (int ww = 0; ww < 8; ++ww) {
        if (ww < wlim) {
            unsigned bits = 0u;
            #pragma unroll
            for (int jj = 0; jj < 32; ++jj) {
                int j = ww * 32 + jj;
                float4 cb = sm->box[j];
                float  ca = sm->area[j];
                float ix1 = fmaxf(mb.x, cb.x);
                float iy1 = fmaxf(mb.y, cb.y);
                float ix2 = fminf(mb.z, cb.z);
                float iy2 = fminf(mb.w, cb.w);
                float dx = fmaxf(ix2 - ix1, 0.0f);
                float dy = fmaxf(iy2 - iy1, 0.0f);
                float t = fmaf(3.0f, dx * dy, -(mya + ca));
                if (t > 0.0f && j < row) bits |= (1u << jj);
            }
            adjw[ww] = bits;
        }
    }

    if (tid < 8) {
        int full = Mp >> 5, rem = Mp & 31;
        unsigned v = (tid < full) ? 0xFFFFFFFFu
                   : (tid == full && rem) ? ((1u << rem) - 1u) : 0u;
        sm->keepw[tid] = v;
        if (tid == 0) sm->chgr = -1;
    }
    __syncthreads();

    // Jacobi fixpoint (2 syncs/round): keep[r] = !exists j<r kept & adjacent.
    for (int round = 0; round < MCAP + 2; ++round) {
        unsigned sup = 0u;
        #pragma unroll
        for (int ww = 0; ww < 8; ++ww) sup |= (sm->keepw[ww] & adjw[ww]);
        bool kp = (row < Mp) && (sup == 0u);
        unsigned nw = __ballot_sync(0xFFFFFFFFu, kp);
        __syncthreads();                        // all reads of keepw done
        if (lane == 0 && nw != sm->keepw[wb]) {
            sm->keepw[wb] = nw;
            sm->chgr = round;                   // benign same-value race
        }
        __syncthreads();                        // writes visible
        if (sm->chgr != round) break;           // no word changed -> fixpoint
    }

    if (tid == 0) {
        int tot = 0;
        #pragma unroll
        for (int ww = 0; ww < 8; ++ww) tot += __popc(sm->keepw[ww]);
        sm->kept = tot;
    }
    __syncthreads();
}

__global__ __launch_bounds__(NT, 6)
void fused_nms_kernel(const float* __restrict__ scores,   // [N,C]
                      const float* __restrict__ boxes_f,  // [N,4]
                      float* __restrict__ out,
                      int N, int C, unsigned magicC) {
    const int tid = threadIdx.x;
    const int nwork = (C < MAX_C) ? C : MAX_C;

    __shared__ SmemAll smem;

    // ================= phase 1: TMA filter, contiguous ownership ==========
    {
        const int totalF  = N * C;
        const int nchunks = totalF / CHUNK_FLOATS;
        const int G = gridDim.x;

        // permute so phase-2 blocks (0..nwork-1) sit at the end of the
        // assignment and never carry the +1 remainder chunk
        const int b  = blockIdx.x;
        const int bp = (b < nwork) ? (G - nwork + b) : (b - nwork);
        const int qc = nchunks / G;
        const int rc = nchunks - qc * G;
        const int cntb  = qc + ((bp < rc) ? 1 : 0);
        const int start = bp * qc + ((bp < rc) ? bp : rc);

        uint32_t mb[NBUF], sb[NBUF];
        #pragma unroll
        for (int k = 0; k < NBUF; ++k) {
            mb[k] = smem_u32(&smem.mbar[k]);
            sb[k] = smem_u32(&smem.buf[k][0]);
        }
        if (tid == 0) {
            #pragma unroll
            for (int k = 0; k < NBUF; ++k) mbar_init(mb[k], 1);
        }
        __syncthreads();

        // issue ALL owned chunks (up to ring depth) immediately
        if (tid == 0) {
            int up = (cntb < NBUF) ? cntb : NBUF;
            for (int k = 0; k < up; ++k)
                tma_issue(sb[k], scores + (long long)(start + k) * CHUNK_FLOATS,
                          mb[k]);
        }

        for (int j = 0; j < cntb; ++j) {
            const int s = j & (NBUF - 1);
            mbar_wait(mb[s], (unsigned)(j >> 2) & 1u);

            const int fbase = (start + j) * CHUNK_FLOATS;
            #pragma unroll
            for (int h = 0; h < 2; ++h) {
                int e = tid + h * NT;
                float4 v = smem.buf[s][e];
                emitv(v, fbase + e * 4, C, magicC);
            }
            __syncthreads();   // readers done before buffer reuse

            int nid = j + NBUF;
            if (tid == 0 && nid < cntb)
                tma_issue(sb[s],
                          scores + (long long)(start + nid) * CHUNK_FLOATS,
                          mb[s]);
        }

        // tail floats (totalF % CHUNK_FLOATS)
        for (int f = nchunks * CHUNK_FLOATS + blockIdx.x * NT + tid;
             f < totalF; f += G * NT) {
            float sc = scores[f];
            if (sc > FINE_LO) {
                int i = f / C;
                int c = f - i * C;
                unsigned pos = atomicAdd(&g_cnt[c], 1u);
                if (pos < CAPBUF)
                    g_pairs[c * CAPBUF + pos] = make_key(sc, (unsigned)i);
            }
        }
    }

    // ================= global barrier =================
    __threadfence();
    __syncthreads();
    if (tid == 0) atomicAdd(&g_bar, 1u);
    if (blockIdx.x >= nwork) return;
    if (tid == 0) {
        while (*(volatile unsigned*)&g_bar < gridDim.x) __nanosleep(128);
        __threadfence();
    }
    __syncthreads();

    // ================= phase 2: per-class NMS ==========
    const int c = blockIdx.x;
    const float4* __restrict__ boxes = (const float4*)boxes_f;
    SmemNMS& sm = smem.nms;

    const unsigned cnt = __ldcg(&g_cnt[c]);
    bool fb = (cnt > (unsigned)MCAP);
    int Mp = 0;

    if (!fb) {
        sm.keys[tid] = (tid < (int)cnt)
                     ? __ldcg(&g_pairs[c * CAPBUF + tid]) : 0ull;
        __syncthreads();
        Mp = (int)cnt;
        nms_core(&sm, boxes, Mp, tid);
        if (sm.kept < K_OUT) fb = true;
        __syncthreads();
    }

    if (fb) {   // exact full-range sweep (statistical tail / adversarial only)
        for (int b2 = tid; b2 < NB_FB; b2 += NT) sm.hist[b2] = 0u;
        if (tid == 0) sm.cnt2 = 0u;
        __syncthreads();

        for (int i = tid; i < N; i += NT) {
            float s = scores[(long long)i * C + c];
            if (s > SCORE_T) {
                int b2 = max(min((int)(s * (float)NB_FB), NB_FB - 1), 0);
                atomicAdd(&sm.hist[b2], 1u);
            }
        }
        __syncthreads();
        const int bmin = (int)(SCORE_T * (float)NB_FB);
        if (tid < 32) warp_cutoff(sm.hist, NB_FB, bmin, &sm.b0);
        __syncthreads();
        const int b0 = sm.b0;

        if (tid == 0) sm.cnt2 = 0u;
        __syncthreads();
        for (int i = tid; i < N; i += NT) {
            float s = scores[(long long)i * C + c];
            if (s > SCORE_T) {
                int b2 = max(min((int)(s * (float)NB_FB), NB_FB - 1), 0);
                if (b2 >= b0) {
                    unsigned pos = atomicAdd(&sm.cnt2, 1u);
                    if (pos < MCAP) sm.keys[pos] = make_key(s, (unsigned)i);
                }
            }
        }
        __syncthreads();
        Mp = (int)min(sm.cnt2, (unsigned)MCAP);
        for (int i = Mp + tid; i < MCAP; i += NT) sm.keys[i] = 0ull;
        __syncthreads();
        nms_core(&sm, boxes, Mp, tid);
    }

    // ---- writeout: concat [scores | classes | boxes | valids] ----
    const int CK = C * K_OUT;
    float*  out_scores  = out;
    float*  out_classes = out + CK;
    float4* out_boxes4  = (float4*)(out + 2 * CK);
    float*  out_valid   = out + 6 * CK;

    const int kept_cap = min(sm.kept, K_OUT);

    const int w    = tid >> 5;
    const int lane = tid & 31;
    const int wb   = (w < 4) ? w : 11 - w;
    const int row  = wb * 32 + lane;

    bool mykeep = (row < Mp) && ((sm.keepw[wb] >> lane) & 1u);
    if (mykeep) {
        const unsigned mbm = lane ? ((1u << lane) - 1u) : 0u;
        int pos = 0;
        #pragma unroll
        for (int ww = 0; ww < 8; ++ww) {
            unsigned x = sm.keepw[ww];
            if (ww < wb)       pos += __popc(x);
            else if (ww == wb) pos += __popc(x & mbm);
        }
        if (pos < K_OUT) {
            int o = c * K_OUT + pos;
            out_scores[o] = sm.score[row];
            out_boxes4[o] = sm.box[row];
        }
    }
    if (tid < K_OUT) {
        int o = c * K_OUT + tid;
        out_classes[o] = (float)c;
        out_valid[o]   = (tid < kept_cap) ? 1.0f : 0.0f;
        if (tid >= kept_cap) {
            out_scores[o] = 0.0f;
            out_boxes4[o] = make_float4(0.f, 0.f, 0.f, 0.f);
        }
    }

    // ---- restore global invariants for the next (graph-replayed) call ----
    __syncthreads();
    if (tid == 0) {
        g_cnt[c] = 0u;
        unsigned d = atomicAdd(&g_done, 1u);
        if (d == (unsigned)(nwork - 1)) { g_bar = 0u; g_done = 0u; }
    }
}

extern "C" void kernel_launch(void* const* d_in, const int* in_sizes, int n_in,
                              void* d_out, int out_size) {
    const float* scores = (const float*)d_in[0];  // [N, C]
    const float* boxes  = (const float*)d_in[1];  // [N, 4]
    float* out = (float*)d_out;

    int N = in_sizes[1] / 4;
    int C = in_sizes[0] / N;
    unsigned magicC = (unsigned)((0x100000000ULL + (unsigned)C - 1)
                                 / (unsigned)C);   // ceil(2^32 / C)

    fused_nms_kernel<<<NBLOCKS, NT>>>(scores, boxes, out, N, C, magicC);
}

// round 11
// speedup vs baseline: 1.1645x; 1.1645x over previous
#include <cuda_runtime.h>
#include <cuda_bf16.h>

// Per-class greedy NMS, round 11 = round-8 filter (best measured) + truncated
// phase 2. Phase 1 (all blocks): strided unroll-4 float4 filter of [N,C]
// scores -> per-class (score,idx) pairs (score > FINE_LO, E ~196/class).
// Global software barrier (888 blocks, 6/SM co-resident).
// Phase 2 (blocks 0..C-1): rank-scatter over all cnt keys -> TRUNCATE row set
// to top-160 (exact: kept<100 triggers the full-sweep fallback, so any class
// where 160 candidates don't suffice is recomputed exactly) -> Mp-bounded
// triangular IoU adjacency (SMSP-balanced) -> 2-sync Jacobi fixpoint ->
// popcount-ranked float4 writeout.

#define MAX_C    80
#define CAPBUF   256
#define NB_FB    2048
#define TOPM     192
#define MCAP     256
#define TRUNC    160
#define K_OUT    100
#define NT       256
#define NBLOCKS  888
#define SCORE_T  0.05f
#define IOU_T    0.5f
#define FINE_LO  0.996f

__device__ unsigned long long g_pairs[MAX_C * CAPBUF];
__device__ unsigned int       g_cnt[MAX_C];   // zero at load; restored each call
__device__ unsigned int       g_bar;
__device__ unsigned int       g_done;

__device__ __forceinline__ unsigned long long make_key(float s, unsigned i) {
    return ((unsigned long long)__float_as_uint(s) << 32)
         | (unsigned long long)(0xFFFFFFFFu - i);
}

__device__ __forceinline__ void emit4(float4 v, int flat0, int C,
                                      unsigned magicC) {
    float m = fmaxf(fmaxf(v.x, v.y), fmaxf(v.z, v.w));
    if (m > FINE_LO) {
        float ss[4] = {v.x, v.y, v.z, v.w};
        #pragma unroll
        for (int u = 0; u < 4; ++u) {
            if (ss[u] > FINE_LO) {
                int flat = flat0 + u;
                unsigned q = (unsigned)(((unsigned long long)(unsigned)flat
                                         * magicC) >> 32);
                int r = flat - (int)q * C;
                if (r < 0)     { --q; r += C; }
                while (r >= C) { ++q; r -= C; }
                unsigned pos = atomicAdd(&g_cnt[r], 1u);
                if (pos < CAPBUF)
                    g_pairs[r * CAPBUF + pos] = make_key(ss[u], q);
            }
        }
    }
}

__device__ __forceinline__ void warp_cutoff(const unsigned int* hist,
                                            int nbucket, int bmin, int* s_b0) {
    const int lane = threadIdx.x;
    int cum = 0, b0 = bmin;
    for (int hi = nbucket - 1; hi >= bmin; hi -= 32) {
        int b = hi - lane;
        int v = (b >= bmin) ? (int)hist[b] : 0;
        int p = v;
        #pragma unroll
        for (int off = 1; off < 32; off <<= 1) {
            int t = __shfl_up_sync(0xFFFFFFFFu, p, off);
            if (lane >= off) p += t;
        }
        unsigned m = __ballot_sync(0xFFFFFFFFu, cum + p >= TOPM);
        if (m) { b0 = hi - (__ffs(m) - 1); break; }
        cum += __shfl_sync(0xFFFFFFFFu, p, 31);
    }
    if (lane == 0) *s_b0 = b0;
}

struct SmemNMS {
    unsigned long long keys[MCAP];
    float4       box[MCAP];
    float        area[MCAP];
    float        score[MCAP];
    unsigned int hist[NB_FB];       // fallback only
    unsigned int keepw[8];
    unsigned int cnt2;
    int          b0, kept, chgr;
};

// rank-scatter over Mfull keys; adjacency/Jacobi truncated to Mp rows.
__device__ __forceinline__ void nms_core(SmemNMS* sm,
                                         const float4* __restrict__ boxes,
                                         int Mfull, int Mp, int tid) {
    const unsigned long long mykey = sm->keys[tid];
    const ulonglong2* __restrict__ k2 = (const ulonglong2*)sm->keys;
    const int jmax = (Mfull + 1) >> 1;    // slots are UNORDERED: scan all keys
    int rank = 0;
    #pragma unroll 4
    for (int j = 0; j < jmax; ++j) {
        ulonglong2 kk = k2[j];
        rank += (kk.x > mykey) ? 1 : 0;
        rank += (kk.y > mykey) ? 1 : 0;
    }
    if (tid < Mfull) {
        int idx = (int)(0xFFFFFFFFu - (unsigned)(mykey & 0xFFFFFFFFull));
        float4 b = __ldg(boxes + idx);
        sm->box[rank]   = b;
        sm->area[rank]  = (b.z - b.x) * (b.w - b.y);
        sm->score[rank] = __uint_as_float((unsigned)(mykey >> 32));
    }
    __syncthreads();

    const int w    = tid >> 5;
    const int lane = tid & 31;
    const int wb   = (w < 4) ? w : 11 - w;   // SMSP-balanced row blocks
    const int row  = wb * 32 + lane;
    const int nwB  = (Mp + 31) >> 5;
    const int wlim = min(wb + 1, nwB);

    const float4 mb  = sm->box[row];
    const float  mya = sm->area[row] + 1e-8f;
    unsigned adjw[8] = {0u,0u,0u,0u,0u,0u,0u,0u};

    // IoU > 0.5  <=>  3*inter > a_i + a_j + 1e-8 (division-free, exact)
    #pragma unroll
    for (int ww = 0; ww < 8; ++ww) {
        if (ww < wlim) {
            unsigned bits = 0u;
            #pragma unroll
            for (int jj = 0; jj < 32; ++jj) {
                int j = ww * 32 + jj;
                float4 cb = sm->box[j];
                float  ca = sm->area[j];
                float ix1 = fmaxf(mb.x, cb.x);
                float iy1 = fmaxf(mb.y, cb.y);
                float ix2 = fminf(mb.z, cb.z);
                float iy2 = fminf(mb.w, cb.w);
                float dx = fmaxf(ix2 - ix1, 0.0f);
                float dy = fmaxf(iy2 - iy1, 0.0f);
                float t = fmaf(3.0f, dx * dy, -(mya + ca));
                if (t > 0.0f && j < row) bits |= (1u << jj);
            }
            adjw[ww] = bits;
        }
    }

    if (tid < 8) {
        int full = Mp >> 5, rem = Mp & 31;
        unsigned v = (tid < full) ? 0xFFFFFFFFu
                   : (tid == full && rem) ? ((1u << rem) - 1u) : 0u;
        sm->keepw[tid] = v;
        if (tid == 0) sm->chgr = -1;
    }
    __syncthreads();

    // Jacobi fixpoint (2 syncs/round): keep[r] = !exists j<r kept & adjacent.
    for (int round = 0; round < MCAP + 2; ++round) {
        unsigned sup = 0u;
        #pragma unroll
        for (int ww = 0; ww < 8; ++ww) sup |= (sm->keepw[ww] & adjw[ww]);
        bool kp = (row < Mp) && (sup == 0u);
        unsigned nw = __ballot_sync(0xFFFFFFFFu, kp);
        __syncthreads();                        // all reads of keepw done
        if (lane == 0 && nw != sm->keepw[wb]) {
            sm->keepw[wb] = nw;
            sm->chgr = round;                   // benign same-value race
        }
        __syncthreads();                        // writes visible
        if (sm->chgr != round) break;           // no word changed -> fixpoint
    }

    if (tid == 0) {
        int tot = 0;
        #pragma unroll
        for (int ww = 0; ww < 8; ++ww) tot += __popc(sm->keepw[ww]);
        sm->kept = tot;
    }
    __syncthreads();
}

__global__ __launch_bounds__(NT, 6)
void fused_nms_kernel(const float* __restrict__ scores,   // [N,C]
                      const float* __restrict__ boxes_f,  // [N,4]
                      float* __restrict__ out,
                      int N, int C, unsigned magicC) {
    const int tid = threadIdx.x;
    const int nwork = (C < MAX_C) ? C : MAX_C;

    // ================= phase 1: strided unroll-4 filter =================
    {
        const int total  = N * C;
        const int total4 = total >> 2;
        const float4* __restrict__ p4 = (const float4*)scores;
        const int T  = gridDim.x * blockDim.x;
        const int j0 = blockIdx.x * blockDim.x + tid;

        for (int b = j0; b < total4; b += 4 * T) {
            float4 v[4];
            bool   h[4];
            #pragma unroll
            for (int q = 0; q < 4; ++q) {
                int idx = b + q * T;
                h[q] = (idx < total4);
                v[q] = h[q] ? p4[idx] : make_float4(0.f, 0.f, 0.f, 0.f);
            }
            #pragma unroll
            for (int q = 0; q < 4; ++q)
                if (h[q]) emit4(v[q], (b + q * T) * 4, C, magicC);
        }
        for (int f = total4 * 4 + j0; f < total; f += T) {
            float s = scores[f];
            if (s > FINE_LO) {
                int i = f / C;
                int c = f - i * C;
                unsigned pos = atomicAdd(&g_cnt[c], 1u);
                if (pos < CAPBUF)
                    g_pairs[c * CAPBUF + pos] = make_key(s, (unsigned)i);
            }
        }
    }

    // ================= global barrier =================
    __threadfence();
    __syncthreads();
    if (tid == 0) atomicAdd(&g_bar, 1u);
    if (blockIdx.x >= nwork) return;
    if (tid == 0) {
        while (*(volatile unsigned*)&g_bar < gridDim.x) __nanosleep(64);
        __threadfence();
    }
    __syncthreads();

    // ================= phase 2: per-class NMS ==========
    const int c = blockIdx.x;
    const float4* __restrict__ boxes = (const float4*)boxes_f;
    __shared__ SmemNMS sm;

    const unsigned cnt = __ldcg(&g_cnt[c]);
    bool fb = (cnt > (unsigned)MCAP);
    int Mp = 0;

    if (!fb) {
        sm.keys[tid] = (tid < (int)cnt)
                     ? __ldcg(&g_pairs[c * CAPBUF + tid]) : 0ull;
        __syncthreads();
        const int Mfull = (int)cnt;
        Mp = min(Mfull, TRUNC);   // exact: insufficient-truncation -> fallback
        nms_core(&sm, boxes, Mfull, Mp, tid);
        if (sm.kept < K_OUT) fb = true;
        __syncthreads();
    }

    if (fb) {   // exact full-range sweep (statistical tail / adversarial only)
        for (int b2 = tid; b2 < NB_FB; b2 += NT) sm.hist[b2] = 0u;
        if (tid == 0) sm.cnt2 = 0u;
        __syncthreads();

        for (int i = tid; i < N; i += NT) {
            float s = scores[(long long)i * C + c];
            if (s > SCORE_T) {
                int b2 = max(min((int)(s * (float)NB_FB), NB_FB - 1), 0);
                atomicAdd(&sm.hist[b2], 1u);
            }
        }
        __syncthreads();
        const int bmin = (int)(SCORE_T * (float)NB_FB);
        if (tid < 32) warp_cutoff(sm.hist, NB_FB, bmin, &sm.b0);
        __syncthreads();
        const int b0 = sm.b0;

        if (tid == 0) sm.cnt2 = 0u;
        __syncthreads();
        for (int i = tid; i < N; i += NT) {
            float s = scores[(long long)i * C + c];
            if (s > SCORE_T) {
                int b2 = max(min((int)(s * (float)NB_FB), NB_FB - 1), 0);
                if (b2 >= b0) {
                    unsigned pos = atomicAdd(&sm.cnt2, 1u);
                    if (pos < MCAP) sm.keys[pos] = make_key(s, (unsigned)i);
                }
            }
        }
        __syncthreads();
        int Mfull = (int)min(sm.cnt2, (unsigned)MCAP);
        for (int i = Mfull + tid; i < MCAP; i += NT) sm.keys[i] = 0ull;
        __syncthreads();
        Mp = Mfull;               // no truncation in the exact path
        nms_core(&sm, boxes, Mfull, Mp, tid);
    }

    // ---- writeout: concat [scores | classes | boxes | valids] ----
    const int CK = C * K_OUT;
    float*  out_scores  = out;
    float*  out_classes = out + CK;
    float4* out_boxes4  = (float4*)(out + 2 * CK);
    float*  out_valid   = out + 6 * CK;

    const int kept_cap = min(sm.kept, K_OUT);

    const int w    = tid >> 5;
    const int lane = tid & 31;
    const int wb   = (w < 4) ? w : 11 - w;
    const int row  = wb * 32 + lane;

    bool mykeep = (row < Mp) && ((sm.keepw[wb] >> lane) & 1u);
    if (mykeep) {
        const unsigned mbm = lane ? ((1u << lane) - 1u) : 0u;
        int pos = 0;
        #pragma unroll
        for (int ww = 0; ww < 8; ++ww) {
            unsigned x = sm.keepw[ww];
            if (ww < wb)       pos += __popc(x);
            else if (ww == wb) pos += __popc(x & mbm);
        }
        if (pos < K_OUT) {
            int o = c * K_OUT + pos;
            out_scores[o] = sm.score[row];
            out_boxes4[o] = sm.box[row];
        }
    }
    if (tid < K_OUT) {
        int o = c * K_OUT + tid;
        out_classes[o] = (float)c;
        out_valid[o]   = (tid < kept_cap) ? 1.0f : 0.0f;
        if (tid >= kept_cap) {
            out_scores[o] = 0.0f;
            out_boxes4[o] = make_float4(0.f, 0.f, 0.f, 0.f);
        }
    }

    // ---- restore global invariants for the next (graph-replayed) call ----
    __syncthreads();
    if (tid == 0) {
        g_cnt[c] = 0u;
        unsigned d = atomicAdd(&g_done, 1u);
        if (d == (unsigned)(nwork - 1)) { g_bar = 0u; g_done = 0u; }
    }
}

extern "C" void kernel_launch(void* const* d_in, const int* in_sizes, int n_in,
                              void* d_out, int out_size) {
    const float* scores = (const float*)d_in[0];  // [N, C]
    const float* boxes  = (const float*)d_in[1];  // [N, 4]
    float* out = (float*)d_out;

    int N = in_sizes[1] / 4;
    int C = in_sizes[0] / N;
    unsigned magicC = (unsigned)((0x100000000ULL + (unsigned)C - 1)
                                 / (unsigned)C);   // ceil(2^32 / C)

    fused_nms_kernel<<<NBLOCKS, NT>>>(scores, boxes, out, N, C, magicC);
}